// round 16
// baseline (speedup 1.0000x reference)
#include <cuda_runtime.h>
#include <cuda_fp16.h>
#include <math.h>
#include <stdint.h>

// Shapes (fixed): B=4, N=256, D=256, H=8, HD=32, DFF=1024
#define BN 1024
#define DD 256

// ---------------- scratch ----------------
__device__ __align__(16) float  g_Hs[BN * DD];    // Hs + bs + be
__device__ __align__(16) float  g_Hd[BN * DD];
__device__ __align__(16) float  g_x1[BN * DD];
__device__ __align__(16) float  g_qkv[BN * 768];
__device__ __align__(16) __half g_biash[4 * 8 * 256 * 256];
__device__ __align__(16) float  g_o[BN * DD];
__device__ __align__(16) float  g_h1[BN * DD];
__device__ __align__(16) float  g_y[BN * DD];
__device__ __align__(16) float  g_ffn[BN * 1024];
__device__ __align__(16) __half g_WeTh[DD * DD];
__device__ __align__(16) __half g_WqkvTh[768 * DD];
__device__ __align__(16) __half g_WoTh[DD * DD];
__device__ __align__(16) __half g_W1Th[1024 * DD];
__device__ __align__(16) __half g_W2Th[DD * 1024];
__device__ __align__(16) __half g_WsTh[DD * DD];
__device__ __align__(16) __half g_WdTh[DD * DD];

// ---------------- streams/events (created at load time) ----------------
struct EdgeStreams {
    cudaStream_t s2;
    cudaEvent_t evT, evD, evQ, evE1, evF;
    EdgeStreams() {
        cudaStreamCreateWithFlags(&s2, cudaStreamNonBlocking);
        cudaEventCreateWithFlags(&evT,  cudaEventDisableTiming);
        cudaEventCreateWithFlags(&evD,  cudaEventDisableTiming);
        cudaEventCreateWithFlags(&evQ,  cudaEventDisableTiming);
        cudaEventCreateWithFlags(&evE1, cudaEventDisableTiming);
        cudaEventCreateWithFlags(&evF,  cudaEventDisableTiming);
    }
};
static EdgeStreams g_str;

// ---------------- helpers ----------------
__device__ __forceinline__ uint32_t smem_u32(const void* p) {
    uint32_t a;
    asm("{ .reg .u64 t; cvta.to.shared.u64 t, %1; cvt.u32.u64 %0, t; }"
        : "=r"(a) : "l"(p));
    return a;
}
__device__ __forceinline__ void cp16(uint32_t dst, const void* src) {
    asm volatile("cp.async.cg.shared.global [%0], [%1], 16;"
                 :: "r"(dst), "l"(src));
}
__device__ __forceinline__ void ldmx4(uint32_t* r, uint32_t addr) {
    asm volatile(
        "ldmatrix.sync.aligned.m8n8.x4.shared.b16 {%0,%1,%2,%3}, [%4];"
        : "=r"(r[0]), "=r"(r[1]), "=r"(r[2]), "=r"(r[3]) : "r"(addr));
}
__device__ __forceinline__ void mma_f16(float* c, const uint32_t* a,
                                        uint32_t b0, uint32_t b1) {
    asm volatile(
        "mma.sync.aligned.m16n8k16.row.col.f32.f16.f16.f32 "
        "{%0,%1,%2,%3}, {%4,%5,%6,%7}, {%8,%9}, {%0,%1,%2,%3};"
        : "+f"(c[0]), "+f"(c[1]), "+f"(c[2]), "+f"(c[3])
        : "r"(a[0]), "r"(a[1]), "r"(a[2]), "r"(a[3]), "r"(b0), "r"(b1));
}
__device__ __forceinline__ uint32_t pack_h2(float x, float y) {
    __half2 h = __float22half2_rn(make_float2(x, y));
    return *reinterpret_cast<uint32_t*>(&h);
}
__device__ __forceinline__ float gelu_exact(float x) {
    return 0.5f * x * (1.0f + erff(x * 0.70710678118654752f));
}

// ---------------- transpose helper ----------------
__device__ __forceinline__ void transpose_tile(
    const float* in, __half* out, int K, int N, int t)
{
    __shared__ float s[32][33];
    const int ntn = N >> 5;
    const int k0 = (t / ntn) << 5, n0 = (t % ntn) << 5;
    const int r = threadIdx.x >> 5, c = threadIdx.x & 31;
    #pragma unroll
    for (int q = 0; q < 4; ++q)
        s[r + q * 8][c] = in[(size_t)(k0 + r + q * 8) * N + n0 + c];
    __syncthreads();
    #pragma unroll
    for (int q = 0; q < 4; ++q)
        out[(size_t)(n0 + r + q * 8) * K + k0 + c] =
            __float2half_rn(s[c][r + q * 8]);
}

__global__ __launch_bounds__(256) void transpose_crit(
    const float* __restrict__ We, const float* __restrict__ Ws,
    __half* __restrict__ oWe, __half* __restrict__ oWs)
{
    int bid = blockIdx.x;
    if (bid < 64) transpose_tile(We, oWe, 256, 256, bid);
    else          transpose_tile(Ws, oWs, 256, 256, bid - 64);
}

__global__ __launch_bounds__(256) void transpose_rest(
    const float* __restrict__ Wd,  const float* __restrict__ Wqkv,
    const float* __restrict__ Wo,  const float* __restrict__ W1,
    const float* __restrict__ W2,
    __half* __restrict__ oWd,  __half* __restrict__ oWqkv,
    __half* __restrict__ oWo,  __half* __restrict__ oW1,
    __half* __restrict__ oW2)
{
    int bid = blockIdx.x;
    if (bid < 64)        transpose_tile(Wd,   oWd,   256,  256,  bid);
    else if (bid < 256)  transpose_tile(Wqkv, oWqkv, 256,  768,  bid - 64);
    else if (bid < 320)  transpose_tile(Wo,   oWo,   256,  256,  bid - 256);
    else if (bid < 576)  transpose_tile(W1,   oW1,   256,  1024, bid - 320);
    else                 transpose_tile(W2,   oW2,   1024, 256,  bid - 576);
}

// ---------------- edge kernel: 64x256 tile, 256 thr, 2 CTAs/SM ----------
#define SB_B     0
#define SB_A     65536
#define SM_SHS   81920
#define SM_SBIAS 82944
#define SM_EDGE_TOTAL 91136

__global__ __launch_bounds__(256, 2) void edge_mma_kernel(
    const float* __restrict__ e, const __half* __restrict__ WeTh,
    const float* __restrict__ Hs, const float* __restrict__ Hd,
    const float* __restrict__ Wb,
    float* __restrict__ e_new, __half* __restrict__ bias, int blk_off)
{
    extern __shared__ char smem[];
    const uint32_t sb = smem_u32(smem);
    float* sHs   = (float*)(smem + SM_SHS);
    float* sbias = (float*)(smem + SM_SBIAS);

    const int tid = threadIdx.x;
    const int w = tid >> 5, lane = tid & 31;
    const int g = lane >> 2, tig = lane & 3, x7 = lane & 7;
    const int wr = w >> 2, wc = w & 3;

    const int m0 = (blockIdx.x + blk_off) * 64;
    const int b = m0 >> 16, i = (m0 >> 8) & 255, j0 = m0 & 255;

    // ---- B chunk 0 (256 n-rows x 64 k) via cp.async ----
    #pragma unroll
    for (int it = 0; it < 8; ++it) {
        int idx = tid + it * 256;
        int r = idx >> 3, ch = idx & 7;
        cp16(sb + SB_B + r * 128 + ((ch ^ (r & 7)) << 4),
             WeTh + (size_t)r * 256 + ch * 8);
    }
    asm volatile("cp.async.commit_group;");

    // ---- A chunk 0: LDG fp32 -> fp16 STS (64 rows x 64 k) ----
    const float* Ab = e + (size_t)m0 * 256;
    #pragma unroll
    for (int p = 0; p < 2; ++p) {
        int idx = tid + p * 256;
        int row = idx >> 3, seg = idx & 7;
        const float* ptr = Ab + (size_t)row * 256 + seg * 8;
        float4 v0 = *(const float4*)ptr;
        float4 v1 = *(const float4*)(ptr + 4);
        uint4 u = make_uint4(pack_h2(v0.x, v0.y), pack_h2(v0.z, v0.w),
                             pack_h2(v1.x, v1.y), pack_h2(v1.z, v1.w));
        *(uint4*)(smem + SB_A + row * 128 + ((seg ^ (row & 7)) << 4)) = u;
    }

    // ---- tables ----
    sHs[tid] = Hs[(((size_t)(b << 8) + i) << 8) + tid];

    asm volatile("cp.async.wait_group 0;" ::: "memory");
    __syncthreads();

    const int rowoffA = x7 + (((lane >> 3) & 1) << 3);
    const int selA = lane >> 4;
    const int rowoffB = x7 + ((lane >> 4) << 3);
    const int selB = (lane >> 3) & 1;

    float acc[2][8][4] = {};
    float4 pre[4];

    for (int c = 0; c < 4; ++c) {
        if (c < 3) {
            #pragma unroll
            for (int it = 0; it < 8; ++it) {
                int idx = tid + it * 256;
                int r = idx >> 3, ch = idx & 7;
                cp16(sb + SB_B + (((c + 1) & 1) << 15) + r * 128 +
                         ((ch ^ (r & 7)) << 4),
                     WeTh + (size_t)r * 256 + (c + 1) * 64 + ch * 8);
            }
            asm volatile("cp.async.commit_group;");
            #pragma unroll
            for (int p = 0; p < 2; ++p) {
                int idx = tid + p * 256;
                int row = idx >> 3, seg = idx & 7;
                const float* ptr =
                    Ab + (size_t)row * 256 + (c + 1) * 64 + seg * 8;
                pre[p * 2]     = *(const float4*)ptr;
                pre[p * 2 + 1] = *(const float4*)(ptr + 4);
            }
        }
        const uint32_t sAc = sb + SB_A + ((c & 1) << 13);
        const uint32_t sBc = sb + SB_B + ((c & 1) << 15);
        #pragma unroll
        for (int kk = 0; kk < 4; ++kk) {
            uint32_t a0[4], a1[4];
            {
                int rowA = wr * 32 + rowoffA;
                ldmx4(a0, sAc + rowA * 128 + ((((kk << 1) + selA) ^ x7) << 4));
                ldmx4(a1, sAc + (rowA + 16) * 128 +
                              ((((kk << 1) + selA) ^ x7) << 4));
            }
            uint32_t bf[4][4];
            #pragma unroll
            for (int nt2 = 0; nt2 < 4; ++nt2) {
                int rowB = wc * 64 + nt2 * 16 + rowoffB;
                ldmx4(bf[nt2], sBc + rowB * 128 +
                               ((((kk << 1) + selB) ^ x7) << 4));
            }
            #pragma unroll
            for (int nt2 = 0; nt2 < 4; ++nt2) {
                mma_f16(acc[0][nt2 * 2],     a0, bf[nt2][0], bf[nt2][1]);
                mma_f16(acc[0][nt2 * 2 + 1], a0, bf[nt2][2], bf[nt2][3]);
                mma_f16(acc[1][nt2 * 2],     a1, bf[nt2][0], bf[nt2][1]);
                mma_f16(acc[1][nt2 * 2 + 1], a1, bf[nt2][2], bf[nt2][3]);
            }
        }
        __syncthreads();
        if (c < 3) {
            char* dst = smem + SB_A + (((c + 1) & 1) << 13);
            #pragma unroll
            for (int p = 0; p < 2; ++p) {
                int idx = tid + p * 256;
                int row = idx >> 3, seg = idx & 7;
                float4 v0 = pre[p * 2], v1 = pre[p * 2 + 1];
                uint4 u = make_uint4(pack_h2(v0.x, v0.y), pack_h2(v0.z, v0.w),
                                     pack_h2(v1.x, v1.y), pack_h2(v1.z, v1.w));
                *(uint4*)(dst + row * 128 + ((seg ^ (row & 7)) << 4)) = u;
            }
            asm volatile("cp.async.wait_group 0;" ::: "memory");
            __syncthreads();
        }
    }
    __syncthreads();   // B stage buffers (64KB @0) now dead -> staging

    const int mtile = w >> 1, khalf = w & 1;
    uint32_t bw0[8], bw1[8];
    #pragma unroll
    for (int kc = 0; kc < 8; ++kc) {
        int k0 = khalf * 128 + kc * 16 + 2 * tig;
        bw0[kc] = pack_h2(Wb[(k0    ) * 8 + g], Wb[(k0 + 1) * 8 + g]);
        bw1[kc] = pack_h2(Wb[(k0 + 8) * 8 + g], Wb[(k0 + 9) * 8 + g]);
    }

    // ---- pass A: stage fp16(acc + Hs) into SB_B, swizzled ----
    char* stg = smem + SB_B;
    #pragma unroll
    for (int mt = 0; mt < 2; ++mt) {
        const int rl = wr * 32 + mt * 16 + g;
        #pragma unroll
        for (int nt = 0; nt < 8; ++nt) {
            const int cl = wc * 64 + nt * 8 + 2 * tig;
            float2 hs = *(const float2*)(sHs + cl);
            uint32_t u0 = pack_h2(acc[mt][nt][0] + hs.x, acc[mt][nt][1] + hs.y);
            uint32_t u1 = pack_h2(acc[mt][nt][2] + hs.x, acc[mt][nt][3] + hs.y);
            const int chunk = wc * 8 + nt;
            *(uint32_t*)(stg + rl * 512 + ((chunk ^ g) << 4) + 4 * tig) = u0;
            *(uint32_t*)(stg + (rl + 8) * 512 + ((chunk ^ g) << 4) + 4 * tig) = u1;
        }
    }
    __syncthreads();

    // ---- pass B: coalesced +Hd, ReLU, e_new store; relu'd fp16 in place --
    {
        const float* hdb = Hd + (((size_t)(b << 8) + j0) << 8);
        float* eb = e_new + (size_t)m0 * 256;
        #pragma unroll
        for (int p = 0; p < 16; ++p) {
            int idx = p * 256 + tid;
            int r = idx >> 6, c4 = idx & 63;
            uint32_t soff = r * 512 + (((c4 >> 1) ^ (r & 7)) << 4) + (c4 & 1) * 8;
            uint2 hv = *(uint2*)(stg + soff);
            float2 f0 = __half22float2(*(__half2*)&hv.x);
            float2 f1 = __half22float2(*(__half2*)&hv.y);
            float4 hd4 = *(const float4*)(hdb + (size_t)r * 256 + c4 * 4);
            float x0 = fmaxf(f0.x + hd4.x, 0.0f);
            float x1 = fmaxf(f0.y + hd4.y, 0.0f);
            float x2 = fmaxf(f1.x + hd4.z, 0.0f);
            float x3 = fmaxf(f1.y + hd4.w, 0.0f);
            *(float4*)(eb + (size_t)r * 256 + c4 * 4) =
                make_float4(x0, x1, x2, x3);
            uint2 wb;
            wb.x = pack_h2(x0, x1);
            wb.y = pack_h2(x2, x3);
            *(uint2*)(stg + soff) = wb;
        }
    }
    __syncthreads();

    // ---- pass C: bias = relu'd x @ Wb via mma from staging ----
    {
        float bc4[4] = {0.0f, 0.0f, 0.0f, 0.0f};
        #pragma unroll
        for (int kk = 0; kk < 8; ++kk) {
            uint32_t a[4];
            int rowA = mtile * 16 + rowoffA;
            ldmx4(a, sb + SB_B + rowA * 512 +
                     (((khalf * 16 + kk * 2 + selA) ^ x7) << 4));
            mma_f16(bc4, a, bw0[kk], bw1[kk]);
        }
        float* sbw = sbias + khalf * 512;
        int rl = mtile * 16 + g;
        sbw[rl * 8 + 2 * tig]           = bc4[0];
        sbw[rl * 8 + 2 * tig + 1]       = bc4[1];
        sbw[(rl + 8) * 8 + 2 * tig]     = bc4[2];
        sbw[(rl + 8) * 8 + 2 * tig + 1] = bc4[3];
    }
    __syncthreads();
    #pragma unroll
    for (int q = 0; q < 2; ++q) {
        int t = tid + q * 256;
        int r = t & 63, hh = t >> 6;
        float v = sbias[r * 8 + hh] + sbias[512 + r * 8 + hh];
        bias[((((size_t)b * 8 + hh) * 256 + i) << 8) + j0 + r] =
            __float2half_rn(v);
    }
}

// ---------------- fp16 MMA GEMM: 64x64 tile, 256 thr (8 warps 2x4) ------
template <int OP, bool RES>
__global__ __launch_bounds__(256) void gemm_mma64(
    const float* __restrict__ A, const __half* __restrict__ Wh,
    const float* __restrict__ bias, const float* __restrict__ bias2,
    const float* __restrict__ res,
    float* __restrict__ out, int K, int N, int my_off)
{
    extern __shared__ char sm2[];
    const uint32_t sb = smem_u32(sm2);
    const int tid = threadIdx.x;
    const int w = tid >> 5, lane = tid & 31;
    const int g = lane >> 2, tig = lane & 3, x7 = lane & 7;
    const int wr = w >> 2, wc = w & 3;
    const int m0 = (blockIdx.y + my_off) * 64, n0 = blockIdx.x * 64;
    const int NC = K >> 6;

    const float*  Ab = A + (size_t)m0 * K;
    const __half* Bb = Wh + (size_t)n0 * K;
    const int arow = tid >> 2;
    const int cpair = tid & 3;

    #pragma unroll
    for (int p = 0; p < 2; ++p) {
        int idx = tid + p * 256;
        int r = idx >> 3, ch = idx & 7;
        cp16(sb + 16384 + r * 128 + ((ch ^ (r & 7)) << 4),
             Bb + (size_t)r * K + ch * 8);
    }
    asm volatile("cp.async.commit_group;");
    #pragma unroll
    for (int q = 0; q < 2; ++q) {
        int ch = cpair * 2 + q;
        const float* p = Ab + (size_t)arow * K + ch * 8;
        float4 v0 = *(const float4*)p;
        float4 v1 = *(const float4*)(p + 4);
        uint4 u = make_uint4(pack_h2(v0.x, v0.y), pack_h2(v0.z, v0.w),
                             pack_h2(v1.x, v1.y), pack_h2(v1.z, v1.w));
        *(uint4*)(sm2 + arow * 128 + ((ch ^ (arow & 7)) << 4)) = u;
    }
    asm volatile("cp.async.wait_group 0;" ::: "memory");
    __syncthreads();

    const int rowoffA = x7 + (((lane >> 3) & 1) << 3);
    const int selA = lane >> 4;
    const int rowoffB = x7 + ((lane >> 4) << 3);
    const int selB = (lane >> 3) & 1;

    float acc[2][2][4] = {};
    float4 pre[4];

    for (int c = 0; c < NC; ++c) {
        if (c + 1 < NC) {
            #pragma unroll
            for (int p = 0; p < 2; ++p) {
                int idx = tid + p * 256;
                int r = idx >> 3, ch = idx & 7;
                cp16(sb + 16384 + (((c + 1) & 1) << 13) + r * 128 +
                         ((ch ^ (r & 7)) << 4),
                     Bb + (size_t)r * K + (c + 1) * 64 + ch * 8);
            }
            asm volatile("cp.async.commit_group;");
            #pragma unroll
            for (int q = 0; q < 2; ++q) {
                int ch = cpair * 2 + q;
                const float* p = Ab + (size_t)arow * K + (c + 1) * 64 + ch * 8;
                pre[q * 2]     = *(const float4*)p;
                pre[q * 2 + 1] = *(const float4*)(p + 4);
            }
        }
        const uint32_t sA = sb + ((c & 1) << 13);
        const uint32_t sB = sb + 16384 + ((c & 1) << 13);
        #pragma unroll
        for (int kk = 0; kk < 4; ++kk) {
            uint32_t a0[4], a1[4];
            int rA = wr * 32 + rowoffA;
            ldmx4(a0, sA + rA * 128 + ((((kk << 1) + selA) ^ x7) << 4));
            ldmx4(a1, sA + (rA + 16) * 128 + ((((kk << 1) + selA) ^ x7) << 4));
            uint32_t bf[4];
            int rB = wc * 16 + rowoffB;
            ldmx4(bf, sB + rB * 128 + ((((kk << 1) + selB) ^ x7) << 4));
            mma_f16(acc[0][0], a0, bf[0], bf[1]);
            mma_f16(acc[0][1], a0, bf[2], bf[3]);
            mma_f16(acc[1][0], a1, bf[0], bf[1]);
            mma_f16(acc[1][1], a1, bf[2], bf[3]);
        }
        __syncthreads();
        if (c + 1 < NC) {
            char* dst = sm2 + (((c + 1) & 1) << 13);
            #pragma unroll
            for (int q = 0; q < 2; ++q) {
                int ch = cpair * 2 + q;
                float4 v0 = pre[q * 2], v1 = pre[q * 2 + 1];
                uint4 u = make_uint4(pack_h2(v0.x, v0.y), pack_h2(v0.z, v0.w),
                                     pack_h2(v1.x, v1.y), pack_h2(v1.z, v1.w));
                *(uint4*)(dst + arow * 128 + ((ch ^ (arow & 7)) << 4)) = u;
            }
            asm volatile("cp.async.wait_group 0;" ::: "memory");
            __syncthreads();
        }
    }

    #pragma unroll
    for (int mt = 0; mt < 2; ++mt) {
        #pragma unroll
        for (int rh = 0; rh < 2; ++rh) {
            int rl = wr * 32 + mt * 16 + rh * 8 + g;
            float* orow = out + (size_t)(m0 + rl) * N + n0;
            const float* rrow = RES ? res + (size_t)(m0 + rl) * N + n0 : nullptr;
            #pragma unroll
            for (int nh = 0; nh < 2; ++nh) {
                int cl = wc * 16 + nh * 8 + 2 * tig;
                float b0 = __ldg(bias + n0 + cl);
                float b1 = __ldg(bias + n0 + cl + 1);
                if (bias2) {
                    b0 += __ldg(bias2 + n0 + cl);
                    b1 += __ldg(bias2 + n0 + cl + 1);
                }
                float x0 = acc[mt][nh][rh * 2 + 0] + b0;
                float x1 = acc[mt][nh][rh * 2 + 1] + b1;
                if (OP == 1) { x0 = gelu_exact(x0); x1 = gelu_exact(x1); }
                if (RES) {
                    float2 rv = *(const float2*)(rrow + cl);
                    x0 += rv.x; x1 += rv.y;
                }
                *(float2*)(orow + cl) = make_float2(x0, x1);
            }
        }
    }
}

// ---------------- LayerNorm ----------------
__global__ __launch_bounds__(256) void ln_kernel(
    const float* __restrict__ in, const float* __restrict__ g,
    const float* __restrict__ b, float* __restrict__ out, int row_off)
{
    int row = blockIdx.x + row_off;
    int t = threadIdx.x;
    float v = in[(size_t)row * 256 + t];
    __shared__ float red[8];

    float s = v;
    #pragma unroll
    for (int o = 16; o; o >>= 1) s += __shfl_xor_sync(0xffffffffu, s, o);
    if ((t & 31) == 0) red[t >> 5] = s;
    __syncthreads();
    float mean = (red[0] + red[1] + red[2] + red[3] +
                  red[4] + red[5] + red[6] + red[7]) * (1.0f / 256.0f);
    float d = v - mean;
    __syncthreads();
    s = d * d;
    #pragma unroll
    for (int o = 16; o; o >>= 1) s += __shfl_xor_sync(0xffffffffu, s, o);
    if ((t & 31) == 0) red[t >> 5] = s;
    __syncthreads();
    float var = (red[0] + red[1] + red[2] + red[3] +
                 red[4] + red[5] + red[6] + red[7]) * (1.0f / 256.0f);
    out[(size_t)row * 256 + t] = d * rsqrtf(var + 1e-5f) * g[t] + b[t];
}

// ---------------- attention kernel: fp16 k/v smem, fp16 bias -------------
__global__ __launch_bounds__(256, 2) void attn_kernel(
    const float* __restrict__ qkv, const __half* __restrict__ bias,
    const float* __restrict__ bb, float* __restrict__ o, int b_off)
{
    extern __shared__ float sm[];
    __half2* ks2 = (__half2*)sm;                 // [256][17]
    __half2* vs2 = ks2 + 256 * 17;               // [256][17]
    float*   qs  = (float*)(vs2 + 256 * 17);     // [16][33]

    const int tid = threadIdx.x;
    const int tile = blockIdx.x & 15;
    const int bh = blockIdx.x >> 4;
    const int b = (bh >> 3) + b_off, hh = bh & 7;
    const int i0 = tile * 16;
    const float bbv = bb[hh];

    #pragma unroll
    for (int it = 0; it < 16; ++it) {
        int idx = tid + it * 256;
        int j = idx >> 4, d2 = idx & 15;
        const float* base = qkv + (size_t)(b * 256 + j) * 768 + hh * 32 + d2 * 2;
        float2 kk = *(const float2*)(base + 256);
        float2 vv = *(const float2*)(base + 512);
        ks2[j * 17 + d2] = __float22half2_rn(kk);
        vs2[j * 17 + d2] = __float22half2_rn(vv);
    }
    #pragma unroll
    for (int it = 0; it < 2; ++it) {
        int idx = tid + it * 256;
        int r = idx >> 5, d = idx & 31;
        qs[r * 33 + d] = qkv[(size_t)(b * 256 + i0 + r) * 768 + hh * 32 + d];
    }
    __syncthreads();

    const int r = tid >> 4, s = tid & 15;
    const int i = i0 + r;
    const __half* brow = bias + ((((size_t)b * 8 + hh) * 256 + i) << 8);

    float q[32];
    #pragma unroll
    for (int d = 0; d < 32; ++d) q[d] = qs[r * 33 + d];

    float sc[16];
    float mx = -1e30f;
    #pragma unroll
    for (int jj = 0; jj < 16; ++jj) {
        int j = jj * 16 + s;
        const __half2* kp = ks2 + j * 17;
        float a = 0.0f;
        #pragma unroll
        for (int d2 = 0; d2 < 16; ++d2) {
            float2 kf = __half22float2(kp[d2]);
            a += q[2 * d2] * kf.x + q[2 * d2 + 1] * kf.y;
        }
        a = a * 0.17677669529663687f + __half2float(brow[j]) + bbv;
        sc[jj] = a;
        mx = fmaxf(mx, a);
    }
    #pragma unroll
    for (int off = 8; off; off >>= 1)
        mx = fmaxf(mx, __shfl_xor_sync(0xffffffffu, mx, off));

    float sum = 0.0f;
    #pragma unroll
    for (int jj = 0; jj < 16; ++jj) {
        sc[jj] = __expf(sc[jj] - mx);
        sum += sc[jj];
    }
    #pragma unroll
    for (int off = 8; off; off >>= 1)
        sum += __shfl_xor_sync(0xffffffffu, sum, off);
    float inv = 1.0f / sum;

    float oacc[32] = {};
    #pragma unroll
    for (int jj = 0; jj < 16; ++jj) {
        int j = jj * 16 + s;
        float wgt = sc[jj];
        const __half2* vp = vs2 + j * 17;
        #pragma unroll
        for (int d2 = 0; d2 < 16; ++d2) {
            float2 vf = __half22float2(vp[d2]);
            oacc[2 * d2]     += wgt * vf.x;
            oacc[2 * d2 + 1] += wgt * vf.y;
        }
    }

    float w2[2];
    #pragma unroll
    for (int d = 0; d < 32; ++d) {
        float t = oacc[d];
        t += __shfl_xor_sync(0xffffffffu, t, 1);
        t += __shfl_xor_sync(0xffffffffu, t, 2);
        t += __shfl_xor_sync(0xffffffffu, t, 4);
        t += __shfl_xor_sync(0xffffffffu, t, 8);
        if ((d >> 1) == s) w2[d & 1] = t;
    }
    *(float2*)(o + ((size_t)(b * 256 + i)) * 256 + hh * 32 + s * 2) =
        make_float2(w2[0] * inv, w2[1] * inv);
}

// ---------------- launch ----------------
extern "C" void kernel_launch(void* const* d_in, const int* in_sizes, int n_in,
                              void* d_out, int out_size)
{
    (void)in_sizes; (void)n_in; (void)out_size;
    const float* h    = (const float*)d_in[0];
    const float* e    = (const float*)d_in[1];
    const float* We   = (const float*)d_in[2];
    const float* be   = (const float*)d_in[3];
    const float* Ws   = (const float*)d_in[4];
    const float* bs   = (const float*)d_in[5];
    const float* Wd   = (const float*)d_in[6];
    const float* bd   = (const float*)d_in[7];
    const float* Wb   = (const float*)d_in[8];
    const float* bb   = (const float*)d_in[9];
    const float* ln1g = (const float*)d_in[10];
    const float* ln1b = (const float*)d_in[11];
    const float* Wqkv = (const float*)d_in[12];
    const float* bqkv = (const float*)d_in[13];
    const float* Wo   = (const float*)d_in[14];
    const float* bo   = (const float*)d_in[15];
    const float* ln2g = (const float*)d_in[16];
    const float* ln2b = (const float*)d_in[17];
    const float* W1   = (const float*)d_in[18];
    const float* b1   = (const float*)d_in[19];
    const float* W2   = (const float*)d_in[20];
    const float* b2   = (const float*)d_in[21];

    float* out_h2 = (float*)d_out;
    float* out_e  = out_h2 + (size_t)BN * DD;

    float *pHs, *pHd, *px1, *pqkv, *po, *ph1, *py, *pf;
    __half *pbiash, *pWeTh, *pWqkvTh, *pWoTh, *pW1Th, *pW2Th, *pWsTh, *pWdTh;
    cudaGetSymbolAddress((void**)&pHs,     g_Hs);
    cudaGetSymbolAddress((void**)&pHd,     g_Hd);
    cudaGetSymbolAddress((void**)&px1,     g_x1);
    cudaGetSymbolAddress((void**)&pqkv,    g_qkv);
    cudaGetSymbolAddress((void**)&pbiash,  g_biash);
    cudaGetSymbolAddress((void**)&po,      g_o);
    cudaGetSymbolAddress((void**)&ph1,     g_h1);
    cudaGetSymbolAddress((void**)&py,      g_y);
    cudaGetSymbolAddress((void**)&pf,      g_ffn);
    cudaGetSymbolAddress((void**)&pWeTh,   g_WeTh);
    cudaGetSymbolAddress((void**)&pWqkvTh, g_WqkvTh);
    cudaGetSymbolAddress((void**)&pWoTh,   g_WoTh);
    cudaGetSymbolAddress((void**)&pW1Th,   g_W1Th);
    cudaGetSymbolAddress((void**)&pW2Th,   g_W2Th);
    cudaGetSymbolAddress((void**)&pWsTh,   g_WsTh);
    cudaGetSymbolAddress((void**)&pWdTh,   g_WdTh);

    cudaStream_t s0 = 0;
    cudaStream_t s2 = g_str.s2;

    cudaFuncSetAttribute(edge_mma_kernel,
                         cudaFuncAttributeMaxDynamicSharedMemorySize,
                         SM_EDGE_TOTAL);

    // ---- fork ----
    cudaEventRecord(g_str.evT, s0);
    cudaStreamWaitEvent(s2, g_str.evT, 0);

    // s0: critical transpose (We, Ws) -> Hs
    transpose_crit<<<128, 256, 0, s0>>>(We, Ws, pWeTh, pWsTh);
    gemm_mma64<0, false><<<dim3(4, 16), 256, 32768, s0>>>(
        h, pWsTh, bs, be, nullptr, pHs, 256, 256, 0);

    // s2: rest transpose (Wd, Wqkv, Wo, W1, W2) -> Hd -> ln1 -> qkv
    transpose_rest<<<832, 256, 0, s2>>>(Wd, Wqkv, Wo, W1, W2,
                                        pWdTh, pWqkvTh, pWoTh, pW1Th, pW2Th);
    gemm_mma64<0, false><<<dim3(4, 16), 256, 32768, s2>>>(
        h, pWdTh, bd, nullptr, nullptr, pHd, 256, 256, 0);
    cudaEventRecord(g_str.evD, s2);
    ln_kernel<<<BN, 256, 0, s2>>>(h, ln1g, ln1b, px1, 0);
    gemm_mma64<0, false><<<dim3(12, 16), 256, 32768, s2>>>(
        px1, pWqkvTh, bqkv, nullptr, nullptr, pqkv, 256, 768, 0);
    cudaEventRecord(g_str.evQ, s2);

    // s0: edge b01 (needs Hs in-order + Hd via evD)
    cudaStreamWaitEvent(s0, g_str.evD, 0);
    edge_mma_kernel<<<2048, 256, SM_EDGE_TOTAL, s0>>>(
        e, pWeTh, pHs, pHd, Wb, out_e, pbiash, 0);
    cudaEventRecord(g_str.evE1, s0);
    // s0: edge b23
    edge_mma_kernel<<<2048, 256, SM_EDGE_TOTAL, s0>>>(
        e, pWeTh, pHs, pHd, Wb, out_e, pbiash, 2048);

    // s2: b01 tail overlapping edge b23 (qkv in-order; bias b01 via evE1)
    cudaStreamWaitEvent(s2, g_str.evE1, 0);
    attn_kernel<<<256, 256, 36928, s2>>>(pqkv, pbiash, bb, po, 0);
    gemm_mma64<0, true><<<dim3(4, 8), 256, 32768, s2>>>(
        po, pWoTh, bo, nullptr, h, ph1, 256, 256, 0);
    ln_kernel<<<512, 256, 0, s2>>>(ph1, ln2g, ln2b, py, 0);
    gemm_mma64<1, false><<<dim3(16, 8), 256, 32768, s2>>>(
        py, pW1Th, b1, nullptr, nullptr, pf, 256, 1024, 0);
    gemm_mma64<0, true><<<dim3(4, 8), 256, 32768, s2>>>(
        pf, pW2Th, b2, nullptr, ph1, out_h2, 1024, 256, 0);
    cudaEventRecord(g_str.evF, s2);

    // s0: b23 tail (qkv via evQ; bias b23 in-order after edge b23)
    cudaStreamWaitEvent(s0, g_str.evQ, 0);
    attn_kernel<<<256, 256, 36928, s0>>>(pqkv, pbiash, bb, po, 2);
    gemm_mma64<0, true><<<dim3(4, 8), 256, 32768, s0>>>(
        po, pWoTh, bo, nullptr, h, ph1, 256, 256, 8);
    ln_kernel<<<512, 256, 0, s0>>>(ph1, ln2g, ln2b, py, 512);
    gemm_mma64<1, false><<<dim3(16, 8), 256, 32768, s0>>>(
        py, pW1Th, b1, nullptr, nullptr, pf, 256, 1024, 8);
    gemm_mma64<0, true><<<dim3(4, 8), 256, 32768, s0>>>(
        pf, pW2Th, b2, nullptr, ph1, out_h2, 1024, 256, 8);

    // join s2 back into s0
    cudaStreamWaitEvent(s0, g_str.evF, 0);
}